// round 1
// baseline (speedup 1.0000x reference)
#include <cuda_runtime.h>
#include <cuda_bf16.h>
#include <math.h>

// Problem constants (fixed by the reference)
#define TOTAL  32768
#define D      1280
#define NSEG   128
#define DHEAD  512

// GEMM tiling
#define BM 128
#define BN 128
#define BK 16
#define TM 8
#define TN 8
#define NTHREADS 256

// ---------------- scratch (static device globals; no allocation) -----------
__device__ float g_s[TOTAL];              // per-row attention logits
__device__ float g_att[TOTAL];            // softmaxed attention weights
__device__ int   g_start[NSEG + 1];       // segment row offsets
__device__ float g_pooled[NSEG * D];      // attention-pooled features
__device__ float g_W1t[D * DHEAD];        // W1 transposed: [k][n]

// ---------------------------------------------------------------------------
// K0: segment boundaries from sorted segment_ids (every segment nonempty)
// ---------------------------------------------------------------------------
__global__ void bounds_kernel(const int* __restrict__ ids) {
    int i = blockIdx.x * blockDim.x + threadIdx.x;
    if (i < TOTAL) {
        if (i == 0) {
            g_start[ids[0]] = 0;
            g_start[NSEG] = TOTAL;
        } else if (ids[i] != ids[i - 1]) {
            g_start[ids[i]] = i;
        }
    }
}

// ---------------------------------------------------------------------------
// K0b: transpose W1 [DHEAD, D] -> W1t [D, DHEAD] for coalesced head reads
// ---------------------------------------------------------------------------
__global__ void transpose_w1_kernel(const float* __restrict__ W1) {
    int idx = blockIdx.x * blockDim.x + threadIdx.x;
    if (idx < DHEAD * D) {
        int n = idx / D;
        int k = idx - n * D;
        g_W1t[k * DHEAD + n] = W1[idx];
    }
}

// ---------------------------------------------------------------------------
// K1: s[i] = sum_j tanh( f[i,:] . Ww[j,:] + bw[j] ) * v[j]
// Fused GEMM (M=TOTAL, N=D, K=D, both operands K-major) + tanh/dot-v epilogue.
// One block per 128-row M tile; loops all 10 N tiles; H never hits HBM.
// Deterministic: fixed-order smem tree reduction (no atomics).
// ---------------------------------------------------------------------------
__global__ void __launch_bounds__(NTHREADS, 2)
gemm_attn_kernel(const float* __restrict__ F,
                 const float* __restrict__ Ww,
                 const float* __restrict__ bw,
                 const float* __restrict__ v) {
    __shared__ float As[BK][BM];
    __shared__ float Bs[BK][BN];
    __shared__ float red[16][BM];

    const int tid = threadIdx.x;
    const int tx = tid & 15;        // 0..15 -> column group
    const int ty = tid >> 4;        // 0..15 -> row group
    const int m0 = blockIdx.x * BM;

    // loader mapping: each thread loads two float4 per operand per K-block
    const int lr = tid >> 2;        // 0..63
    const int lc = (tid & 3) * 4;   // 0,4,8,12

    float srow[TM];
#pragma unroll
    for (int i = 0; i < TM; ++i) srow[i] = 0.f;

    const int NKB = D / BK;         // 80

    for (int nt = 0; nt < D / BN; ++nt) {   // 10 column tiles
        float acc[TM][TN];
#pragma unroll
        for (int i = 0; i < TM; ++i)
#pragma unroll
            for (int j = 0; j < TN; ++j) acc[i][j] = 0.f;

        const float* Ab = F + (size_t)(m0) * D;
        const float* Bb = Ww + (size_t)(nt * BN) * D;

        // prefetch K-block 0
        float4 a0 = *(const float4*)(Ab + (size_t)lr * D + lc);
        float4 a1 = *(const float4*)(Ab + (size_t)(lr + 64) * D + lc);
        float4 b0 = *(const float4*)(Bb + (size_t)lr * D + lc);
        float4 b1 = *(const float4*)(Bb + (size_t)(lr + 64) * D + lc);

        for (int kb = 0; kb < NKB; ++kb) {
            __syncthreads();
            // store prefetched regs to smem (transposed to [k][row])
            As[lc + 0][lr] = a0.x; As[lc + 1][lr] = a0.y;
            As[lc + 2][lr] = a0.z; As[lc + 3][lr] = a0.w;
            As[lc + 0][lr + 64] = a1.x; As[lc + 1][lr + 64] = a1.y;
            As[lc + 2][lr + 64] = a1.z; As[lc + 3][lr + 64] = a1.w;
            Bs[lc + 0][lr] = b0.x; Bs[lc + 1][lr] = b0.y;
            Bs[lc + 2][lr] = b0.z; Bs[lc + 3][lr] = b0.w;
            Bs[lc + 0][lr + 64] = b1.x; Bs[lc + 1][lr + 64] = b1.y;
            Bs[lc + 2][lr + 64] = b1.z; Bs[lc + 3][lr + 64] = b1.w;
            __syncthreads();

            // prefetch next K-block (overlaps with compute below)
            if (kb + 1 < NKB) {
                int k0 = (kb + 1) * BK;
                a0 = *(const float4*)(Ab + (size_t)lr * D + k0 + lc);
                a1 = *(const float4*)(Ab + (size_t)(lr + 64) * D + k0 + lc);
                b0 = *(const float4*)(Bb + (size_t)lr * D + k0 + lc);
                b1 = *(const float4*)(Bb + (size_t)(lr + 64) * D + k0 + lc);
            }

#pragma unroll
            for (int k = 0; k < BK; ++k) {
                float af[TM], bf[TN];
                float4 t0 = *(const float4*)&As[k][ty * TM];
                float4 t1 = *(const float4*)&As[k][ty * TM + 4];
                af[0] = t0.x; af[1] = t0.y; af[2] = t0.z; af[3] = t0.w;
                af[4] = t1.x; af[5] = t1.y; af[6] = t1.z; af[7] = t1.w;
                float4 u0 = *(const float4*)&Bs[k][tx * TN];
                float4 u1 = *(const float4*)&Bs[k][tx * TN + 4];
                bf[0] = u0.x; bf[1] = u0.y; bf[2] = u0.z; bf[3] = u0.w;
                bf[4] = u1.x; bf[5] = u1.y; bf[6] = u1.z; bf[7] = u1.w;
#pragma unroll
                for (int i = 0; i < TM; ++i)
#pragma unroll
                    for (int j = 0; j < TN; ++j)
                        acc[i][j] = fmaf(af[i], bf[j], acc[i][j]);
            }
        }

        // epilogue for this column tile: srow += tanh(acc + bw) * v
        const int n0 = nt * BN + tx * TN;
#pragma unroll
        for (int j = 0; j < TN; ++j) {
            float bwj = __ldg(&bw[n0 + j]);
            float vj  = __ldg(&v[n0 + j]);
#pragma unroll
            for (int i = 0; i < TM; ++i)
                srow[i] += tanhf(acc[i][j] + bwj) * vj;
        }
    }

    // deterministic cross-tx reduction of srow
    __syncthreads();
#pragma unroll
    for (int i = 0; i < TM; ++i) red[tx][ty * TM + i] = srow[i];
    __syncthreads();
    if (tid < BM) {
        float t = 0.f;
#pragma unroll
        for (int x = 0; x < 16; ++x) t += red[x][tid];
        g_s[m0 + tid] = t;
    }
}

// ---------------------------------------------------------------------------
// K2: per-segment stable softmax over g_s -> g_att  (one block per segment)
// ---------------------------------------------------------------------------
__global__ void softmax_kernel() {
    __shared__ float sm[256];
    const int b = blockIdx.x;
    const int tid = threadIdx.x;
    const int s0 = g_start[b], s1 = g_start[b + 1];

    // max
    float m = -1e30f;
    for (int i = s0 + tid; i < s1; i += 256) m = fmaxf(m, g_s[i]);
    sm[tid] = m;
    __syncthreads();
    for (int st = 128; st >= 1; st >>= 1) {
        if (tid < st) sm[tid] = fmaxf(sm[tid], sm[tid + st]);
        __syncthreads();
    }
    m = sm[0];
    __syncthreads();

    // sum of exp
    float z = 0.f;
    for (int i = s0 + tid; i < s1; i += 256) z += expf(g_s[i] - m);
    sm[tid] = z;
    __syncthreads();
    for (int st = 128; st >= 1; st >>= 1) {
        if (tid < st) sm[tid] += sm[tid + st];
        __syncthreads();
    }
    float inv = 1.f / sm[0];

    for (int i = s0 + tid; i < s1; i += 256)
        g_att[i] = expf(g_s[i] - m) * inv;
}

// ---------------------------------------------------------------------------
// K3: pooled[seg,d] = sum_{i in seg} att[i] * F[i,d]
// grid (D/128 chunks, NSEG); sequential per-thread loop (deterministic)
// ---------------------------------------------------------------------------
__global__ void pool_kernel(const float* __restrict__ F) {
    const int seg = blockIdx.y;
    const int col = blockIdx.x * 128 + threadIdx.x;
    const int s0 = g_start[seg], s1 = g_start[seg + 1];
    float acc = 0.f;
    int i = s0;
    for (; i + 3 < s1; i += 4) {
        float a0 = g_att[i + 0], a1 = g_att[i + 1];
        float a2 = g_att[i + 2], a3 = g_att[i + 3];
        float f0 = F[(size_t)(i + 0) * D + col];
        float f1 = F[(size_t)(i + 1) * D + col];
        float f2 = F[(size_t)(i + 2) * D + col];
        float f3 = F[(size_t)(i + 3) * D + col];
        acc = fmaf(a0, f0, acc);
        acc = fmaf(a1, f1, acc);
        acc = fmaf(a2, f2, acc);
        acc = fmaf(a3, f3, acc);
    }
    for (; i < s1; ++i) acc = fmaf(g_att[i], F[(size_t)i * D + col], acc);
    g_pooled[seg * D + col] = acc;
}

// ---------------------------------------------------------------------------
// K4: head. out[seg] = relu(pooled[seg]@W1^T + b1) @ W2^T + b2
// one block per segment, 512 threads (one per hidden unit), W1t coalesced
// ---------------------------------------------------------------------------
__global__ void __launch_bounds__(DHEAD)
head_kernel(const float* __restrict__ b1,
            const float* __restrict__ W2,
            const float* __restrict__ b2,
            float* __restrict__ out) {
    __shared__ float p[D];
    __shared__ float red[DHEAD];
    const int seg = blockIdx.x;
    const int t = threadIdx.x;

    for (int k = t; k < D; k += DHEAD) p[k] = g_pooled[seg * D + k];
    __syncthreads();

    float acc = 0.f;
#pragma unroll 8
    for (int k = 0; k < D; ++k)
        acc = fmaf(p[k], g_W1t[k * DHEAD + t], acc);

    float h = fmaxf(acc + b1[t], 0.f);
    red[t] = h * W2[t];
    __syncthreads();
    for (int st = DHEAD / 2; st >= 1; st >>= 1) {
        if (t < st) red[t] += red[t + st];
        __syncthreads();
    }
    if (t == 0) out[seg] = red[0] + b2[0];
}

// ---------------------------------------------------------------------------
extern "C" void kernel_launch(void* const* d_in, const int* in_sizes, int n_in,
                              void* d_out, int out_size) {
    const float* features = (const float*)d_in[0];
    const float* Ww       = (const float*)d_in[1];
    const float* bw       = (const float*)d_in[2];
    const float* v        = (const float*)d_in[3];
    const float* W1       = (const float*)d_in[4];
    const float* b1       = (const float*)d_in[5];
    const float* W2       = (const float*)d_in[6];
    const float* b2       = (const float*)d_in[7];
    const int*   seg_ids  = (const int*)d_in[8];
    float* out = (float*)d_out;

    bounds_kernel<<<TOTAL / 256, 256>>>(seg_ids);
    transpose_w1_kernel<<<(DHEAD * D + 255) / 256, 256>>>(W1);
    gemm_attn_kernel<<<TOTAL / BM, NTHREADS>>>(features, Ww, bw, v);
    softmax_kernel<<<NSEG, 256>>>();
    pool_kernel<<<dim3(D / 128, NSEG), 128>>>(features);
    head_kernel<<<NSEG, DHEAD>>>(b1, W2, b2, out);
}

// round 3
// speedup vs baseline: 3.5636x; 3.5636x over previous
#include <cuda_runtime.h>
#include <cuda_bf16.h>
#include <math.h>
#include <stdint.h>

// Problem constants
#define TOTAL  32768
#define D      1280
#define NSEG   128
#define DHEAD  512

// GEMM tiling
#define TILE_M   128
#define TILE_N   128
#define KCH      64                 // K elements per chunk (128B bf16 row)
#define NT_TILES (D / TILE_N)       // 10
#define MT_TILES (TOTAL / TILE_M)   // 256
#define KCHUNKS  (D / KCH)          // 20
#define ATILE_B  (TILE_M * 128)     // 16384
#define BTILE_B  (TILE_N * 128)     // 16384
#define STAGE_B  (2 * ATILE_B + 2 * BTILE_B)   // 65536
#define NSTAGES  3
#define DSMEM    (NSTAGES * STAGE_B + 1024)    // + alignment slack

// ---------------- scratch (static device globals; no allocation) -----------
__device__ float g_s[TOTAL];
__device__ float g_spart[NT_TILES * TOTAL];
__device__ float g_att[TOTAL];
__device__ int   g_start[NSEG + 1];
__device__ float g_pooled[NSEG * D];
__device__ float g_W1t[D * DHEAD];
// split-bf16 operands, tile-contiguous + SW128 pre-swizzled
__device__ __align__(1024) unsigned char g_Fhi[(size_t)TOTAL * D * 2];
__device__ __align__(1024) unsigned char g_Flo[(size_t)TOTAL * D * 2];
__device__ __align__(1024) unsigned char g_Whi[(size_t)D * D * 2];
__device__ __align__(1024) unsigned char g_Wlo[(size_t)D * D * 2];

// ---------------------------- PTX helpers ----------------------------------
__device__ __forceinline__ uint32_t smem_u32(const void* p) {
    uint32_t a;
    asm("{ .reg .u64 t; cvta.to.shared.u64 t, %1; cvt.u32.u64 %0, t; }"
        : "=r"(a) : "l"(p));
    return a;
}
__device__ __forceinline__ uint32_t swz128(uint32_t b) {
    return b ^ ((b >> 3) & 0x70);
}

#define MBARRIER_INIT(addr, cnt) \
    asm volatile("mbarrier.init.shared.b64 [%0], %1;" :: "r"(addr), "r"(cnt) : "memory")
#define MBARRIER_EXPECT_TX(addr, bytes) \
    asm volatile("mbarrier.arrive.expect_tx.shared.b64 _, [%0], %1;" :: "r"(addr), "r"(bytes) : "memory")
#define MBARRIER_WAIT_PARITY(addr, par) do {                                   \
    uint32_t _m = (addr); uint32_t _p = (par); uint32_t _d;                    \
    asm volatile("{\n\t.reg .pred p;\n\t"                                      \
        "mbarrier.try_wait.parity.acquire.cta.shared::cta.b64 p, [%1], %2;\n\t"\
        "selp.b32 %0, 1, 0, p;\n\t}" : "=r"(_d) : "r"(_m), "r"(_p) : "memory");\
    if (!_d) {                                                                 \
        asm volatile("{\n\t.reg .pred P1;\n\t"                                 \
        "WL_%=:\n\t"                                                           \
        "mbarrier.try_wait.parity.acquire.cta.shared::cta.b64 P1, [%0], %1, 0x989680;\n\t"\
        "@P1 bra.uni WD_%=;\n\t"                                               \
        "bra.uni WL_%=;\n\t"                                                   \
        "WD_%=:\n\t}" :: "r"(_m), "r"(_p) : "memory");                         \
    }                                                                          \
} while (0)

__device__ __forceinline__ void bulk_cp(uint32_t dst, const void* src,
                                        uint32_t bytes, uint32_t mbar) {
    asm volatile(
        "cp.async.bulk.shared::cluster.global.mbarrier::complete_tx::bytes [%0], [%1], %2, [%3];"
        :: "r"(dst), "l"(src), "r"(bytes), "r"(mbar) : "memory");
}

#define LDSM4(r, addr) \
    asm volatile("ldmatrix.sync.aligned.m8n8.x4.shared.b16 {%0,%1,%2,%3}, [%4];" \
        : "=r"((r)[0]), "=r"((r)[1]), "=r"((r)[2]), "=r"((r)[3]) : "r"(addr))

#define MMA16816(c, a, b0, b1) \
    asm volatile("mma.sync.aligned.m16n8k16.row.col.f32.bf16.bf16.f32 " \
        "{%0,%1,%2,%3}, {%4,%5,%6,%7}, {%8,%9}, {%0,%1,%2,%3};" \
        : "+f"((c)[0]), "+f"((c)[1]), "+f"((c)[2]), "+f"((c)[3]) \
        : "r"((a)[0]), "r"((a)[1]), "r"((a)[2]), "r"((a)[3]), "r"(b0), "r"(b1))

// ---------------------------------------------------------------------------
// K0: segment boundaries
// ---------------------------------------------------------------------------
__global__ void bounds_kernel(const int* __restrict__ ids) {
    int i = blockIdx.x * blockDim.x + threadIdx.x;
    if (i < TOTAL) {
        if (i == 0) { g_start[ids[0]] = 0; g_start[NSEG] = TOTAL; }
        else if (ids[i] != ids[i - 1]) g_start[ids[i]] = i;
    }
}

// K0b: transpose W1
__global__ void transpose_w1_kernel(const float* __restrict__ W1) {
    int idx = blockIdx.x * blockDim.x + threadIdx.x;
    if (idx < DHEAD * D) {
        int n = idx / D, k = idx - n * D;
        g_W1t[k * DHEAD + n] = W1[idx];
    }
}

// ---------------------------------------------------------------------------
// Kc: split-bf16 conversion into tile-contiguous, pre-swizzled layout.
// ---------------------------------------------------------------------------
__device__ __forceinline__ void split8(const float* x, uint4& hi, uint4& lo) {
    uint32_t h[4], l[4];
#pragma unroll
    for (int j = 0; j < 4; ++j) {
        float a = x[2 * j], b = x[2 * j + 1];
        __nv_bfloat162 hp = __floats2bfloat162_rn(a, b);
        float la = a - __bfloat162float(__low2bfloat16(hp));
        float lb = b - __bfloat162float(__high2bfloat16(hp));
        __nv_bfloat162 lp = __floats2bfloat162_rn(la, lb);
        h[j] = *(uint32_t*)&hp;
        l[j] = *(uint32_t*)&lp;
    }
    hi = make_uint4(h[0], h[1], h[2], h[3]);
    lo = make_uint4(l[0], l[1], l[2], l[3]);
}

__global__ void convF_kernel(const float* __restrict__ F) {
    int idx = blockIdx.x * blockDim.x + threadIdx.x;   // TOTAL * 160
    if (idx >= TOTAL * (D / 8)) return;
    int row = idx / (D / 8), cg = idx - row * (D / 8);
    int mt = row >> 7, r = row & 127;
    int kc = cg >> 3, gi = cg & 7;
    float x[8];
    const float4* src = (const float4*)(F + (size_t)row * D + cg * 8);
    float4 x0 = src[0], x1 = src[1];
    x[0]=x0.x; x[1]=x0.y; x[2]=x0.z; x[3]=x0.w; x[4]=x1.x; x[5]=x1.y; x[6]=x1.z; x[7]=x1.w;
    uint4 hi, lo; split8(x, hi, lo);
    size_t base = (size_t)(mt * KCHUNKS + kc) * ATILE_B;
    uint32_t off = swz128((uint32_t)(r * 128 + gi * 16));
    *(uint4*)(g_Fhi + base + off) = hi;
    *(uint4*)(g_Flo + base + off) = lo;
}

__global__ void convW_kernel(const float* __restrict__ W) {
    int idx = blockIdx.x * blockDim.x + threadIdx.x;   // D * 160
    if (idx >= D * (D / 8)) return;
    int row = idx / (D / 8), cg = idx - row * (D / 8);
    int nt = row >> 7, r = row & 127;
    int kc = cg >> 3, gi = cg & 7;
    float x[8];
    const float4* src = (const float4*)(W + (size_t)row * D + cg * 8);
    float4 x0 = src[0], x1 = src[1];
    x[0]=x0.x; x[1]=x0.y; x[2]=x0.z; x[3]=x0.w; x[4]=x1.x; x[5]=x1.y; x[6]=x1.z; x[7]=x1.w;
    uint4 hi, lo; split8(x, hi, lo);
    size_t base = (size_t)(nt * KCHUNKS + kc) * BTILE_B;
    uint32_t off = swz128((uint32_t)(r * 128 + gi * 16));
    *(uint4*)(g_Whi + base + off) = hi;
    *(uint4*)(g_Wlo + base + off) = lo;
}

// ---------------------------------------------------------------------------
// K1: mma.sync bf16 split GEMM + tanh/dot-v epilogue.
// grid = 256 mt x 10 nt. 8 warps (4m x 2n), warp tile 32x64.
// 3-pass: AhiBhi + AhiBlo + AloBhi (fp32 accumulate).
// ---------------------------------------------------------------------------
__global__ void __launch_bounds__(256, 1)
gemm_tc_kernel(const float* __restrict__ bw, const float* __restrict__ v) {
    extern __shared__ __align__(16) char smem_raw[];
    __shared__ __align__(8) unsigned long long mbar[NSTAGES];
    __shared__ float red[2][TILE_M];

    const uint32_t TILES = (smem_u32(smem_raw) + 1023) & ~1023u;
    const uint32_t MB = smem_u32(&mbar[0]);

    const int tid = threadIdx.x, wid = tid >> 5, lane = tid & 31;
    const int mt = blockIdx.x / NT_TILES, nt = blockIdx.x % NT_TILES;
    const int wm = wid >> 1, wn = wid & 1;

    if (tid == 0) {
#pragma unroll
        for (int s = 0; s < NSTAGES; ++s) MBARRIER_INIT(MB + s * 8, 1);
    }
    __syncthreads();

    const unsigned char* aHi = g_Fhi + (size_t)mt * KCHUNKS * ATILE_B;
    const unsigned char* aLo = g_Flo + (size_t)mt * KCHUNKS * ATILE_B;
    const unsigned char* bHi = g_Whi + (size_t)nt * KCHUNKS * BTILE_B;
    const unsigned char* bLo = g_Wlo + (size_t)nt * KCHUNKS * BTILE_B;

    if (tid == 0) {
#pragma unroll
        for (int k = 0; k < NSTAGES - 1; ++k) {
            uint32_t st = TILES + k * STAGE_B;
            MBARRIER_EXPECT_TX(MB + k * 8, (uint32_t)STAGE_B);
            bulk_cp(st,                 aHi + (size_t)k * ATILE_B, ATILE_B, MB + k * 8);
            bulk_cp(st + ATILE_B,       aLo + (size_t)k * ATILE_B, ATILE_B, MB + k * 8);
            bulk_cp(st + 2 * ATILE_B,   bHi + (size_t)k * BTILE_B, BTILE_B, MB + k * 8);
            bulk_cp(st + 3 * ATILE_B,   bLo + (size_t)k * BTILE_B, BTILE_B, MB + k * 8);
        }
    }

    // per-lane ldmatrix address components (within tile, swizzled)
    const uint32_t xm = (lane & 7) << 4;                    // swizzle XOR mask
    const uint32_t a_rb = (uint32_t)(wm * 32 + (lane & 15)) * 128;
    const uint32_t a_cb = (uint32_t)((lane >> 4) * 16);
    const uint32_t b_rb = (uint32_t)(wn * 64 + (lane & 7) + ((lane >> 4) & 1) * 8) * 128;
    const uint32_t b_cb = (uint32_t)(((lane >> 3) & 1) * 16);

    float acc[2][8][4];
#pragma unroll
    for (int t = 0; t < 2; ++t)
#pragma unroll
        for (int j = 0; j < 8; ++j)
#pragma unroll
            for (int e = 0; e < 4; ++e) acc[t][j][e] = 0.f;

    for (int k = 0; k < KCHUNKS; ++k) {
        const int s = k % NSTAGES;
        MBARRIER_WAIT_PARITY(MB + s * 8, (uint32_t)((k / NSTAGES) & 1));
        const uint32_t st = TILES + s * STAGE_B;

#pragma unroll
        for (int q = 0; q < 4; ++q) {
            uint32_t Ah[2][4], Al[2][4], Bh[4][4], Bl[4][4];
#pragma unroll
            for (int t = 0; t < 2; ++t) {
                uint32_t off = a_rb + t * 2048 + ((q * 32 + a_cb) ^ xm);
                LDSM4(Ah[t], st + off);
                LDSM4(Al[t], st + ATILE_B + off);
            }
#pragma unroll
            for (int g = 0; g < 4; ++g) {
                uint32_t off = b_rb + g * 2048 + ((q * 32 + b_cb) ^ xm);
                LDSM4(Bh[g], st + 2 * ATILE_B + off);
                LDSM4(Bl[g], st + 3 * ATILE_B + off);
            }
#pragma unroll
            for (int t = 0; t < 2; ++t)
#pragma unroll
                for (int g = 0; g < 4; ++g)
#pragma unroll
                    for (int h = 0; h < 2; ++h) {
                        float* c = acc[t][g * 2 + h];
                        MMA16816(c, Ah[t], Bh[g][h * 2], Bh[g][h * 2 + 1]);
                        MMA16816(c, Ah[t], Bl[g][h * 2], Bl[g][h * 2 + 1]);
                        MMA16816(c, Al[t], Bh[g][h * 2], Bh[g][h * 2 + 1]);
                    }
        }
        __syncthreads();
        if (tid == 0 && k + NSTAGES - 1 < KCHUNKS) {
            const int kn = k + NSTAGES - 1;
            const int s2 = kn % NSTAGES;
            uint32_t st2 = TILES + s2 * STAGE_B;
            MBARRIER_EXPECT_TX(MB + s2 * 8, (uint32_t)STAGE_B);
            bulk_cp(st2,               aHi + (size_t)kn * ATILE_B, ATILE_B, MB + s2 * 8);
            bulk_cp(st2 + ATILE_B,     aLo + (size_t)kn * ATILE_B, ATILE_B, MB + s2 * 8);
            bulk_cp(st2 + 2 * ATILE_B, bHi + (size_t)kn * BTILE_B, BTILE_B, MB + s2 * 8);
            bulk_cp(st2 + 3 * ATILE_B, bLo + (size_t)kn * BTILE_B, BTILE_B, MB + s2 * 8);
        }
    }

    // epilogue: srow[r] = sum_n tanh(acc + bw[n]) * v[n], reduced across lanes
    // c-frag layout (m16n8): lane l -> rows (l>>2, l>>2+8), cols (l&3)*2, +1
#pragma unroll
    for (int t = 0; t < 2; ++t) {
        float s0 = 0.f, s1 = 0.f;
#pragma unroll
        for (int j = 0; j < 8; ++j) {
            int n0 = nt * TILE_N + wn * 64 + j * 8 + (lane & 3) * 2;
            float bw0 = __ldg(&bw[n0]),     v0 = __ldg(&v[n0]);
            float bw1 = __ldg(&bw[n0 + 1]), v1 = __ldg(&v[n0 + 1]);
            s0 += tanhf(acc[t][j][0] + bw0) * v0 + tanhf(acc[t][j][1] + bw1) * v1;
            s1 += tanhf(acc[t][j][2] + bw0) * v0 + tanhf(acc[t][j][3] + bw1) * v1;
        }
        s0 += __shfl_xor_sync(0xFFFFFFFFu, s0, 1);
        s0 += __shfl_xor_sync(0xFFFFFFFFu, s0, 2);
        s1 += __shfl_xor_sync(0xFFFFFFFFu, s1, 1);
        s1 += __shfl_xor_sync(0xFFFFFFFFu, s1, 2);
        if ((lane & 3) == 0) {
            int r = wm * 32 + t * 16 + (lane >> 2);
            red[wn][r] = s0;
            red[wn][r + 8] = s1;
        }
    }
    __syncthreads();
    if (tid < TILE_M)
        g_spart[nt * TOTAL + mt * TILE_M + tid] = red[0][tid] + red[1][tid];
}

// K1b: reduce s partials across the 10 N-tiles
__global__ void sreduce_kernel() {
    int i = blockIdx.x * blockDim.x + threadIdx.x;
    if (i < TOTAL) {
        float t = 0.f;
#pragma unroll
        for (int nt = 0; nt < NT_TILES; ++nt) t += g_spart[nt * TOTAL + i];
        g_s[i] = t;
    }
}

// ---------------------------------------------------------------------------
// K2: per-segment stable softmax
// ---------------------------------------------------------------------------
__global__ void softmax_kernel() {
    __shared__ float sm[256];
    const int b = blockIdx.x, tid = threadIdx.x;
    const int s0 = g_start[b], s1 = g_start[b + 1];
    float m = -1e30f;
    for (int i = s0 + tid; i < s1; i += 256) m = fmaxf(m, g_s[i]);
    sm[tid] = m; __syncthreads();
    for (int st = 128; st >= 1; st >>= 1) {
        if (tid < st) sm[tid] = fmaxf(sm[tid], sm[tid + st]);
        __syncthreads();
    }
    m = sm[0]; __syncthreads();
    float z = 0.f;
    for (int i = s0 + tid; i < s1; i += 256) z += expf(g_s[i] - m);
    sm[tid] = z; __syncthreads();
    for (int st = 128; st >= 1; st >>= 1) {
        if (tid < st) sm[tid] += sm[tid + st];
        __syncthreads();
    }
    float inv = 1.f / sm[0];
    for (int i = s0 + tid; i < s1; i += 256)
        g_att[i] = expf(g_s[i] - m) * inv;
}

// ---------------------------------------------------------------------------
// K3: attention-weighted pooling
// ---------------------------------------------------------------------------
__global__ void pool_kernel(const float* __restrict__ F) {
    const int seg = blockIdx.y;
    const int col = blockIdx.x * 128 + threadIdx.x;
    const int s0 = g_start[seg], s1 = g_start[seg + 1];
    float acc = 0.f;
    int i = s0;
    for (; i + 3 < s1; i += 4) {
        float a0 = g_att[i], a1 = g_att[i + 1], a2 = g_att[i + 2], a3 = g_att[i + 3];
        float f0 = F[(size_t)(i + 0) * D + col];
        float f1 = F[(size_t)(i + 1) * D + col];
        float f2 = F[(size_t)(i + 2) * D + col];
        float f3 = F[(size_t)(i + 3) * D + col];
        acc = fmaf(a0, f0, acc); acc = fmaf(a1, f1, acc);
        acc = fmaf(a2, f2, acc); acc = fmaf(a3, f3, acc);
    }
    for (; i < s1; ++i) acc = fmaf(g_att[i], F[(size_t)i * D + col], acc);
    g_pooled[seg * D + col] = acc;
}

// ---------------------------------------------------------------------------
// K4: MLP head
// ---------------------------------------------------------------------------
__global__ void __launch_bounds__(DHEAD)
head_kernel(const float* __restrict__ b1, const float* __restrict__ W2,
            const float* __restrict__ b2, float* __restrict__ out) {
    __shared__ float p[D];
    __shared__ float red[DHEAD];
    const int seg = blockIdx.x, t = threadIdx.x;
    for (int k = t; k < D; k += DHEAD) p[k] = g_pooled[seg * D + k];
    __syncthreads();
    float acc = 0.f;
#pragma unroll 8
    for (int k = 0; k < D; ++k) acc = fmaf(p[k], g_W1t[k * DHEAD + t], acc);
    float h = fmaxf(acc + b1[t], 0.f);
    red[t] = h * W2[t];
    __syncthreads();
    for (int st = DHEAD / 2; st >= 1; st >>= 1) {
        if (t < st) red[t] += red[t + st];
        __syncthreads();
    }
    if (t == 0) out[seg] = red[0] + b2[0];
}

// ---------------------------------------------------------------------------
extern "C" void kernel_launch(void* const* d_in, const int* in_sizes, int n_in,
                              void* d_out, int out_size) {
    const float* features = (const float*)d_in[0];
    const float* Ww       = (const float*)d_in[1];
    const float* bw       = (const float*)d_in[2];
    const float* v        = (const float*)d_in[3];
    const float* W1       = (const float*)d_in[4];
    const float* b1       = (const float*)d_in[5];
    const float* W2       = (const float*)d_in[6];
    const float* b2       = (const float*)d_in[7];
    const int*   seg_ids  = (const int*)d_in[8];
    float* out = (float*)d_out;

    cudaFuncSetAttribute(gemm_tc_kernel,
                         cudaFuncAttributeMaxDynamicSharedMemorySize, DSMEM);

    bounds_kernel<<<TOTAL / 256, 256>>>(seg_ids);
    transpose_w1_kernel<<<(DHEAD * D + 255) / 256, 256>>>(W1);
    convF_kernel<<<(TOTAL * (D / 8) + 255) / 256, 256>>>(features);
    convW_kernel<<<(D * (D / 8) + 255) / 256, 256>>>(Ww);
    gemm_tc_kernel<<<MT_TILES * NT_TILES, 256, DSMEM>>>(bw, v);
    sreduce_kernel<<<TOTAL / 256, 256>>>();
    softmax_kernel<<<NSEG, 256>>>();
    pool_kernel<<<dim3(D / 128, NSEG), 128>>>(features);
    head_kernel<<<NSEG, DHEAD>>>(b1, W2, b2, out);
}